// round 1
// baseline (speedup 1.0000x reference)
#include <cuda_runtime.h>
#include <cstdint>

#define B_   4
#define L_   2048
#define D_   256
#define H_   8
#define HD_  64
#define SCALE 0.125f               // HD^-0.5
#define INV_ML (1.0f/2048.0f)

// scratch for projected Q/K in [h][b][l][hd] layout (16 MB each)
__device__ float Qg[H_*B_*L_*HD_];
__device__ float Kg[H_*B_*L_*HD_];

// ---- packed f32x2 helpers (sm_103a FFMA2 via PTX) ----
__device__ __forceinline__ unsigned long long ffma2(unsigned long long a,
                                                    unsigned long long b,
                                                    unsigned long long c) {
    unsigned long long d;
    asm("fma.rn.f32x2 %0, %1, %2, %3;" : "=l"(d) : "l"(a), "l"(b), "l"(c));
    return d;
}
__device__ __forceinline__ unsigned long long pack2(float lo, float hi) {
    unsigned long long r;
    asm("mov.b64 %0, {%1, %2};" : "=l"(r) : "f"(lo), "f"(hi));
    return r;
}
__device__ __forceinline__ void unpack2(unsigned long long a, float& x, float& y) {
    asm("mov.b64 {%0, %1}, %2;" : "=f"(x), "=f"(y) : "l"(a));
}

// ============================================================
// Kernel 1: projections.  C[8192,512] = x[8192,256] @ W[256,512] (+bias)
// z==0 -> Q (Wq,bq), z==1 -> K (Wk,bk).  Output in [h][b][l][hd].
// 128x128 tile, 256 threads, 8x8 per thread, FFMA2.
// ============================================================
__global__ __launch_bounds__(256) void proj_kernel(
    const float* __restrict__ x,
    const float* __restrict__ Wq, const float* __restrict__ bq,
    const float* __restrict__ Wk, const float* __restrict__ bk)
{
    __shared__ float xs[32][132];   // [kk][row]
    __shared__ float ws[32][128];   // [kk][col]

    const int tid = threadIdx.x;
    const int tx  = tid & 15;       // col group
    const int ty  = tid >> 4;       // row group
    const int r0  = blockIdx.x * 128;
    const int c0  = blockIdx.y * 128;
    const float* W    = (blockIdx.z == 0) ? Wq : Wk;
    const float* bias = (blockIdx.z == 0) ? bq : bk;
    float*       out  = (blockIdx.z == 0) ? Qg : Kg;

    unsigned long long acc[8][4];
#pragma unroll
    for (int i = 0; i < 8; i++)
#pragma unroll
        for (int j = 0; j < 4; j++) acc[i][j] = 0ull;

    for (int d0 = 0; d0 < D_; d0 += 32) {
        // x tile, transposed into [kk][row]
#pragma unroll
        for (int i = 0; i < 4; i++) {
            int idx = i * 256 + tid;          // 1024 float4 = 128 rows x 8 kk-blocks
            int c   = idx & 127;              // row in tile (lanes -> consecutive rows)
            int kb  = idx >> 7;               // 0..7
            float4 v = *(const float4*)(x + (size_t)(r0 + c) * D_ + d0 + kb * 4);
            xs[kb*4+0][c] = v.x; xs[kb*4+1][c] = v.y;
            xs[kb*4+2][c] = v.z; xs[kb*4+3][c] = v.w;
        }
        // w tile, natural [kk][col]
#pragma unroll
        for (int i = 0; i < 4; i++) {
            int idx = i * 256 + tid;          // 1024 float4 = 32 kk x 32 col4
            int kk  = idx >> 5;
            int c4  = idx & 31;
            *(float4*)&ws[kk][c4*4] =
                *(const float4*)(W + (size_t)(d0 + kk) * 512 + c0 + c4 * 4);
        }
        __syncthreads();

#pragma unroll 8
        for (int kk = 0; kk < 32; kk++) {
            ulonglong2 kpa = *(const ulonglong2*)&ws[kk][tx*8];
            ulonglong2 kpb = *(const ulonglong2*)&ws[kk][tx*8+4];
            unsigned long long kp0 = kpa.x, kp1 = kpa.y, kp2 = kpb.x, kp3 = kpb.y;
            float4 qa = *(const float4*)&xs[kk][ty*8];
            float4 qb = *(const float4*)&xs[kk][ty*8+4];
            float qf[8] = {qa.x,qa.y,qa.z,qa.w,qb.x,qb.y,qb.z,qb.w};
#pragma unroll
            for (int i = 0; i < 8; i++) {
                unsigned long long qp = pack2(qf[i], qf[i]);
                acc[i][0] = ffma2(qp, kp0, acc[i][0]);
                acc[i][1] = ffma2(qp, kp1, acc[i][1]);
                acc[i][2] = ffma2(qp, kp2, acc[i][2]);
                acc[i][3] = ffma2(qp, kp3, acc[i][3]);
            }
        }
        __syncthreads();
    }

    // store into [h][b][l][hd]
#pragma unroll
    for (int i = 0; i < 8; i++) {
        int r    = r0 + ty * 8 + i;
        int bidx = r >> 11;            // / 2048
        int l    = r & 2047;
#pragma unroll
        for (int j = 0; j < 4; j++) {
            float s0, s1; unpack2(acc[i][j], s0, s1);
            int c  = c0 + tx * 8 + j * 2;
            int h  = c >> 6;
            int hd = c & 63;
            float* o = out + ((size_t)(h * B_ + bidx) * L_ + l) * HD_ + hd;
            o[0] = s0 + bias[c];
            o[1] = s1 + bias[c + 1];
        }
    }
}

// ============================================================
// Kernel 2: flash-style distance attention.
// Block = (q-tile of 128, (h,b)).  256 threads, 8x8 S-elements/thread.
// Online softmax per thread slice; merge over 16 lanes at the end.
// ============================================================
__global__ __launch_bounds__(256) void flash_kernel(
    const float* __restrict__ prior_mean,
    const float* __restrict__ log_prior_std,
    float* __restrict__ out)
{
    extern __shared__ float sm[];
    float (*Qs)[132] = (float(*)[132])sm;                 // [64 kk][128 rows]
    float (*Ks)[132] = (float(*)[132])(sm + 64 * 132);    // [64 kk][128 cols]
    float* ptab = sm + 2 * 64 * 132;                      // 4095 entries

    const int tid = threadIdx.x;
    const int tx  = tid & 15;
    const int ty  = tid >> 4;
    const int q0  = blockIdx.x * 128;
    const int h   = blockIdx.y >> 2;
    const int bb  = blockIdx.y & 3;

    // per-head prior table: ptab[d+2047] = SCALE * N(d/2048; mean, std)
    {
        float mean    = prior_mean[h];
        float stdv    = __expf(log_prior_std[h]);
        float inv_std = 1.0f / stdv;
        float cnorm   = SCALE * inv_std * 0.3989422917f;   // 1/sqrt(2*3.1415926)
        for (int t = tid; t < 4095; t += 256) {
            float dd = (float)(t - 2047) * INV_ML;
            float z  = (dd - mean) * inv_std;
            ptab[t]  = cnorm * __expf(-0.5f * z * z);
        }
    }

    // load Q tile, transposed [kk][row]
    const float* Qbase = Qg + ((size_t)(h * B_ + bb) * L_ + q0) * HD_;
#pragma unroll
    for (int i = 0; i < 8; i++) {
        int idx = i * 256 + tid;        // 2048 float4 = 128 rows x 16 kk-blocks
        int c   = idx & 127;
        int kb  = idx >> 7;             // 0..15
        float4 v = *(const float4*)(Qbase + (size_t)c * HD_ + kb * 4);
        Qs[kb*4+0][c] = v.x; Qs[kb*4+1][c] = v.y;
        Qs[kb*4+2][c] = v.z; Qs[kb*4+3][c] = v.w;
    }

    const float* Kbase = Kg + (size_t)(h * B_ + bb) * L_ * HD_;

    float m_[8], l_[8], sd_[8];
#pragma unroll
    for (int i = 0; i < 8; i++) { m_[i] = -1e30f; l_[i] = 0.f; sd_[i] = 0.f; }

    __syncthreads();

    for (int kt = 0; kt < L_ / 128; kt++) {
        const int k0 = kt * 128;
        // load K tile, transposed [kk][col]
#pragma unroll
        for (int i = 0; i < 8; i++) {
            int idx = i * 256 + tid;
            int c   = idx & 127;
            int kb  = idx >> 7;
            float4 v = *(const float4*)(Kbase + (size_t)(k0 + c) * HD_ + kb * 4);
            Ks[kb*4+0][c] = v.x; Ks[kb*4+1][c] = v.y;
            Ks[kb*4+2][c] = v.z; Ks[kb*4+3][c] = v.w;
        }
        __syncthreads();

        unsigned long long acc[8][4];
#pragma unroll
        for (int i = 0; i < 8; i++)
#pragma unroll
            for (int j = 0; j < 4; j++) acc[i][j] = 0ull;

#pragma unroll 4
        for (int kk = 0; kk < HD_; kk++) {
            ulonglong2 kpa = *(const ulonglong2*)&Ks[kk][tx*8];
            ulonglong2 kpb = *(const ulonglong2*)&Ks[kk][tx*8+4];
            unsigned long long kp0 = kpa.x, kp1 = kpa.y, kp2 = kpb.x, kp3 = kpb.y;
            float4 qa = *(const float4*)&Qs[kk][ty*8];
            float4 qb = *(const float4*)&Qs[kk][ty*8+4];
            float qf[8] = {qa.x,qa.y,qa.z,qa.w,qb.x,qb.y,qb.z,qb.w};
#pragma unroll
            for (int i = 0; i < 8; i++) {
                unsigned long long qp = pack2(qf[i], qf[i]);
                acc[i][0] = ffma2(qp, kp0, acc[i][0]);
                acc[i][1] = ffma2(qp, kp1, acc[i][1]);
                acc[i][2] = ffma2(qp, kp2, acc[i][2]);
                acc[i][3] = ffma2(qp, kp3, acc[i][3]);
            }
        }

        // epilogue: prior, online softmax, distance-weighted sums
        const int colg = k0 + tx * 8;
#pragma unroll
        for (int i = 0; i < 8; i++) {
            int qrow  = q0 + ty * 8 + i;
            int dbase = colg - qrow;
            float s[8];
#pragma unroll
            for (int j = 0; j < 4; j++) {
                float a0, a1; unpack2(acc[i][j], a0, a1);
                s[2*j]   = a0 * ptab[dbase + 2*j     + 2047];
                s[2*j+1] = a1 * ptab[dbase + 2*j + 1 + 2047];
            }
            float tmax = s[0];
#pragma unroll
            for (int j = 1; j < 8; j++) tmax = fmaxf(tmax, s[j]);
            float mnew  = fmaxf(m_[i], tmax);
            float alpha = __expf(m_[i] - mnew);
            float li = l_[i] * alpha, si = sd_[i] * alpha;
#pragma unroll
            for (int j = 0; j < 8; j++) {
                float p = __expf(s[j] - mnew);
                li += p;
                si += p * ((float)(dbase + j) * INV_ML);
            }
            m_[i] = mnew; l_[i] = li; sd_[i] = si;
        }
        __syncthreads();
    }

    // merge online-softmax state across the 16 lanes owning each row
#pragma unroll
    for (int i = 0; i < 8; i++) {
        float m = m_[i], l = l_[i], s = sd_[i];
#pragma unroll
        for (int off = 8; off >= 1; off >>= 1) {
            float m2 = __shfl_xor_sync(0xffffffffu, m, off, 16);
            float l2 = __shfl_xor_sync(0xffffffffu, l, off, 16);
            float s2 = __shfl_xor_sync(0xffffffffu, s, off, 16);
            float mo = fmaxf(m, m2);
            float e1 = __expf(m - mo), e2 = __expf(m2 - mo);
            l = l * e1 + l2 * e2;
            s = s * e1 + s2 * e2;
            m = mo;
        }
        if (tx == 0) {
            int qrow = q0 + ty * 8 + i;
            out[((size_t)bb * L_ + qrow) * H_ + h] = s / l;
        }
    }
}

// ============================================================
extern "C" void kernel_launch(void* const* d_in, const int* in_sizes, int n_in,
                              void* d_out, int out_size)
{
    const float* x  = (const float*)d_in[0];
    const float* Wq = (const float*)d_in[1];
    const float* bq = (const float*)d_in[2];
    const float* Wk = (const float*)d_in[3];
    const float* bk = (const float*)d_in[4];
    const float* pm = (const float*)d_in[5];
    const float* ls = (const float*)d_in[6];
    float* out = (float*)d_out;

    // projections: 64 row-tiles x 4 col-tiles x {Q,K}
    dim3 pgrid(64, 4, 2);
    proj_kernel<<<pgrid, 256>>>(x, Wq, bq, Wk, bk);

    // flash distance attention: 16 q-tiles x 32 (h,b)
    const int smem_bytes = (2 * 64 * 132 + 4095) * (int)sizeof(float);  // 83964
    cudaFuncSetAttribute(flash_kernel,
                         cudaFuncAttributeMaxDynamicSharedMemorySize, smem_bytes);
    dim3 fgrid(16, 32);
    flash_kernel<<<fgrid, 256, smem_bytes>>>(pm, ls, out);
}

// round 3
// speedup vs baseline: 3.8911x; 3.8911x over previous
#include <cuda_runtime.h>
#include <cuda_bf16.h>
#include <cstdint>

#define B_   4
#define L_   2048
#define H_   8
#define HD_  64
#define SCALE 0.125f
#define INV_ML (1.0f/2048.0f)

// ---------- device scratch ----------
__device__ __nv_bfloat16 xh_g[8192*256];
__device__ __nv_bfloat16 xl_g[8192*256];
__device__ __nv_bfloat16 Wth_g[1024*256];   // [Wq^T ; Wk^T], rows=n, cols=k
__device__ __nv_bfloat16 Wtl_g[1024*256];
__device__ __nv_bfloat16 Qh_g[32*2048*64];  // [h*4+b][l][hd]
__device__ __nv_bfloat16 Ql_g[32*2048*64];
__device__ __nv_bfloat16 Kh_g[32*2048*64];
__device__ __nv_bfloat16 Kl_g[32*2048*64];
__device__ float ptab_g[H_*4095];           // per-head SCALE*prior LUT

// ---------- helpers ----------
__device__ __forceinline__ void split2(float a, float b, uint32_t& hi, uint32_t& lo) {
    __nv_bfloat16 ah = __float2bfloat16(a), bh = __float2bfloat16(b);
    float ar = a - __bfloat162float(ah), br = b - __bfloat162float(bh);
    __nv_bfloat162 h2; h2.x = ah; h2.y = bh;
    __nv_bfloat162 l2; l2.x = __float2bfloat16(ar); l2.y = __float2bfloat16(br);
    hi = *(uint32_t*)&h2; lo = *(uint32_t*)&l2;
}

__device__ __forceinline__ void mma_bf16(float c[4], const uint32_t a[4],
                                         const uint32_t b[2]) {
    asm volatile(
        "mma.sync.aligned.m16n8k16.row.col.f32.bf16.bf16.f32 "
        "{%0,%1,%2,%3}, {%4,%5,%6,%7}, {%8,%9}, {%0,%1,%2,%3};"
        : "+f"(c[0]), "+f"(c[1]), "+f"(c[2]), "+f"(c[3])
        : "r"(a[0]), "r"(a[1]), "r"(a[2]), "r"(a[3]), "r"(b[0]), "r"(b[1]));
}

__device__ __forceinline__ void cpa16(uint32_t d, const void* s) {
    asm volatile("cp.async.cg.shared.global [%0], [%1], 16;" :: "r"(d), "l"(s));
}
__device__ __forceinline__ void cpa_commit() {
    asm volatile("cp.async.commit_group;" ::: "memory");
}
__device__ __forceinline__ void cpa_wait0() {
    asm volatile("cp.async.wait_group 0;" ::: "memory");
}

// ============================================================
// prep kernels
// ============================================================
__global__ __launch_bounds__(512) void ptab_kernel(const float* __restrict__ pm,
                                                   const float* __restrict__ ls) {
    int h = blockIdx.x;
    float mean = pm[h];
    float inv_std = __expf(-ls[h]);
    float cnorm = SCALE * inv_std * 0.39894228f;
    for (int t = threadIdx.x; t < 4095; t += 512) {
        float dd = (float)(t - 2047) * INV_ML;
        float z = (dd - mean) * inv_std;
        ptab_g[h * 4095 + t] = cnorm * __expf(-0.5f * z * z);
    }
}

__global__ __launch_bounds__(256) void conv_x_kernel(const float* __restrict__ x) {
    int i = blockIdx.x * 256 + threadIdx.x;   // float4 index, 524288 total
    float4 v = ((const float4*)x)[i];
    uint32_t h0, l0, h1, l1;
    split2(v.x, v.y, h0, l0);
    split2(v.z, v.w, h1, l1);
    ((uint2*)xh_g)[i] = make_uint2(h0, h1);
    ((uint2*)xl_g)[i] = make_uint2(l0, l1);
}

__global__ void conv_w_kernel(const float* __restrict__ Wq,
                              const float* __restrict__ Wk) {
    __shared__ float t[32][33];
    const float* W = blockIdx.z ? Wk : Wq;
    int n0 = blockIdx.x * 32, k0 = blockIdx.y * 32;
    int tx = threadIdx.x, ty = threadIdx.y;
#pragma unroll
    for (int i = 0; i < 32; i += 8)
        t[ty + i][tx] = W[(size_t)(k0 + ty + i) * 512 + n0 + tx];
    __syncthreads();
#pragma unroll
    for (int i = 0; i < 32; i += 8) {
        int n = n0 + ty + i, k = k0 + tx;
        float v = t[tx][ty + i];
        __nv_bfloat16 h = __float2bfloat16(v);
        float r = v - __bfloat162float(h);
        size_t o = (size_t)(blockIdx.z * 512 + n) * 256 + k;
        Wth_g[o] = h;
        Wtl_g[o] = __float2bfloat16(r);
    }
}

// ============================================================
// proj: [xh|xl][8192,256] @ Wt^T -> Q/K hi/lo bf16 in [h][b][l][hd]
// CTA 128x128, 8 warps (4 mg x 2 ng), warp 32m x 64n, mma.sync bf16 3-split
// ============================================================
#define PJ_SMEM (18432*4)

__global__ __launch_bounds__(256) void proj_kernel(const float* __restrict__ bq,
                                                   const float* __restrict__ bk) {
    extern __shared__ uint32_t sm[];
    uint32_t* As_h = sm;            // [128][36]
    uint32_t* As_l = sm + 4608;
    uint32_t* Bs_h = sm + 9216;
    uint32_t* Bs_l = sm + 13824;

    const int tid = threadIdx.x;
    const int w = tid >> 5, lane = tid & 31, tg = lane >> 2, tm = lane & 3;
    const int mg = w & 3, ng = w >> 2;
    const int m0 = blockIdx.x * 128, n0 = blockIdx.y * 128;

    float acc[2][8][4];
#pragma unroll
    for (int mb = 0; mb < 2; mb++)
#pragma unroll
        for (int nb = 0; nb < 8; nb++)
#pragma unroll
            for (int j = 0; j < 4; j++) acc[mb][nb][j] = 0.f;

    for (int c = 0; c < 4; c++) {
        if (c) __syncthreads();
#pragma unroll
        for (int i = 0; i < 4; i++) {
            int idx = i * 256 + tid;
            int row = idx >> 3, c4 = idx & 7;
            size_t goA = (size_t)(m0 + row) * 256 + c * 64 + c4 * 8;
            size_t goB = (size_t)(n0 + row) * 256 + c * 64 + c4 * 8;
            int so = row * 36 + c4 * 4;
            *(uint4*)(As_h + so) = *(const uint4*)(xh_g + goA);
            *(uint4*)(As_l + so) = *(const uint4*)(xl_g + goA);
            *(uint4*)(Bs_h + so) = *(const uint4*)(Wth_g + goB);
            *(uint4*)(Bs_l + so) = *(const uint4*)(Wtl_g + goB);
        }
        __syncthreads();

#pragma unroll
        for (int ks = 0; ks < 4; ks++) {
            const int ci = ks * 8 + tm;
            uint32_t ah[2][4], al[2][4];
#pragma unroll
            for (int mb = 0; mb < 2; mb++) {
                int rr = 32 * mg + 16 * mb + tg;
                ah[mb][0] = As_h[rr * 36 + ci];
                ah[mb][1] = As_h[(rr + 8) * 36 + ci];
                ah[mb][2] = As_h[rr * 36 + ci + 4];
                ah[mb][3] = As_h[(rr + 8) * 36 + ci + 4];
                al[mb][0] = As_l[rr * 36 + ci];
                al[mb][1] = As_l[(rr + 8) * 36 + ci];
                al[mb][2] = As_l[rr * 36 + ci + 4];
                al[mb][3] = As_l[(rr + 8) * 36 + ci + 4];
            }
#pragma unroll
            for (int nb = 0; nb < 8; nb++) {
                int rn = 64 * ng + 8 * nb + tg;
                uint32_t bh[2] = { Bs_h[rn * 36 + ci], Bs_h[rn * 36 + ci + 4] };
                uint32_t bl[2] = { Bs_l[rn * 36 + ci], Bs_l[rn * 36 + ci + 4] };
#pragma unroll
                for (int mb = 0; mb < 2; mb++) {
                    mma_bf16(acc[mb][nb], ah[mb], bh);
                    mma_bf16(acc[mb][nb], ah[mb], bl);
                    mma_bf16(acc[mb][nb], al[mb], bh);
                }
            }
        }
    }

    // epilogue: bias, split, scatter to [h][b][l][hd]
#pragma unroll
    for (int mb = 0; mb < 2; mb++) {
        int r0 = m0 + 32 * mg + 16 * mb + tg;
#pragma unroll
        for (int nb = 0; nb < 8; nb++) {
            float* a = acc[mb][nb];
            int gcol = n0 + 64 * ng + 8 * nb + 2 * tm;
            int isK = gcol >> 9;
            const float* bias = isK ? bk : bq;
            int bi = gcol & 511;
            float b0 = bias[bi], b1 = bias[bi + 1];
            __nv_bfloat16* dh = isK ? Kh_g : Qh_g;
            __nv_bfloat16* dl = isK ? Kl_g : Ql_g;
            int hh = bi >> 6;
#pragma unroll
            for (int half = 0; half < 2; half++) {
                int r = r0 + 8 * half;
                int bb = r >> 11, l = r & 2047;
                float v0 = a[half * 2 + 0] + b0;
                float v1 = a[half * 2 + 1] + b1;
                uint32_t hi, lo;
                split2(v0, v1, hi, lo);
                size_t e = ((size_t)((hh * 4 + bb) * 2048 + l)) * 64 + (gcol & 63);
                *(uint32_t*)(dh + e) = hi;
                *(uint32_t*)(dl + e) = lo;
            }
        }
    }
}

// ============================================================
// flash: per (q-tile 128, h, b): S = Q K^T (3-split mma.sync),
// prior LUT (__ldg) + exp + distance-weighted reduction, no S materialization.
// ============================================================
#define FL_SMEM (18432*4 + 1024)

__global__ __launch_bounds__(256) void flash_kernel(float* __restrict__ out) {
    extern __shared__ uint32_t sm[];
    float* merge = (float*)(sm + 18432);   // 256 floats

    const int tid = threadIdx.x;
    const int w = tid >> 5, lane = tid & 31, tg = lane >> 2, tm = lane & 3;
    const int mg = w & 3, ng = w >> 2;
    const int q0 = blockIdx.x * 128;
    const int hb = blockIdx.y;
    const int h = hb >> 2;
    const size_t hb_off = (size_t)hb * 2048;

    uint32_t smbase = (uint32_t)__cvta_generic_to_shared(sm);

    // prologue: async-load K tile 0 (hi+lo)
    {
        const char* gh = (const char*)(Kh_g + hb_off * 64);
        const char* gl = (const char*)(Kl_g + hb_off * 64);
#pragma unroll
        for (int i = 0; i < 4; i++) {
            int idx = i * 256 + tid;
            int row = idx >> 3, c4 = idx & 7;
            uint32_t so = (uint32_t)(row * 36 + c4 * 4) * 4;
            cpa16(smbase + so, gh + row * 128 + c4 * 16);
            cpa16(smbase + 18432 + so, gl + row * 128 + c4 * 16);
        }
        cpa_commit();
    }

    // Q A-fragments into registers (once)
    uint32_t aqh[2][4][4], aql[2][4][4];
#pragma unroll
    for (int mb = 0; mb < 2; mb++) {
        int r0 = q0 + 32 * mg + 16 * mb + tg;
        const uint32_t* ph0 = (const uint32_t*)(Qh_g + (hb_off + r0) * 64);
        const uint32_t* ph1 = ph0 + 8 * 32;
        const uint32_t* pl0 = (const uint32_t*)(Ql_g + (hb_off + r0) * 64);
        const uint32_t* pl1 = pl0 + 8 * 32;
#pragma unroll
        for (int ks = 0; ks < 4; ks++) {
            int ci = ks * 8 + tm;
            aqh[mb][ks][0] = ph0[ci];     aqh[mb][ks][1] = ph1[ci];
            aqh[mb][ks][2] = ph0[ci + 4]; aqh[mb][ks][3] = ph1[ci + 4];
            aql[mb][ks][0] = pl0[ci];     aql[mb][ks][1] = pl1[ci];
            aql[mb][ks][2] = pl0[ci + 4]; aql[mb][ks][3] = pl1[ci + 4];
        }
    }

    cpa_wait0();
    __syncthreads();

    float suml[4] = {0.f, 0.f, 0.f, 0.f};
    float sumd[4] = {0.f, 0.f, 0.f, 0.f};
    const float* pt = ptab_g + h * 4095 + 2047;

    for (int kt = 0; kt < 16; kt++) {
        const int buf = kt & 1;
        if (kt < 15) {   // prefetch next K tile into other buffer
            const int k1 = (kt + 1) * 128;
            const char* gh = (const char*)(Kh_g + (hb_off + k1) * 64);
            const char* gl = (const char*)(Kl_g + (hb_off + k1) * 64);
            uint32_t dsth = smbase + (uint32_t)((buf ^ 1) * 2 + 0) * 18432;
            uint32_t dstl = smbase + (uint32_t)((buf ^ 1) * 2 + 1) * 18432;
#pragma unroll
            for (int i = 0; i < 4; i++) {
                int idx = i * 256 + tid;
                int row = idx >> 3, c4 = idx & 7;
                uint32_t so = (uint32_t)(row * 36 + c4 * 4) * 4;
                cpa16(dsth + so, gh + row * 128 + c4 * 16);
                cpa16(dstl + so, gl + row * 128 + c4 * 16);
            }
            cpa_commit();
        }

        const uint32_t* Kh = sm + (buf * 2 + 0) * 4608;
        const uint32_t* Kl = sm + (buf * 2 + 1) * 4608;

        float acc[2][8][4];
#pragma unroll
        for (int mb = 0; mb < 2; mb++)
#pragma unroll
            for (int nb = 0; nb < 8; nb++)
#pragma unroll
                for (int j = 0; j < 4; j++) acc[mb][nb][j] = 0.f;

#pragma unroll
        for (int ks = 0; ks < 4; ks++) {
            const int ci = ks * 8 + tm;
#pragma unroll
            for (int nb = 0; nb < 8; nb++) {
                int rn = 64 * ng + 8 * nb + tg;
                uint32_t bh[2] = { Kh[rn * 36 + ci], Kh[rn * 36 + ci + 4] };
                uint32_t bl[2] = { Kl[rn * 36 + ci], Kl[rn * 36 + ci + 4] };
#pragma unroll
                for (int mb = 0; mb < 2; mb++) {
                    mma_bf16(acc[mb][nb], aqh[mb][ks], bh);
                    mma_bf16(acc[mb][nb], aqh[mb][ks], bl);
                    mma_bf16(acc[mb][nb], aql[mb][ks], bh);
                }
            }
        }

        // epilogue: prior * score, exp, accumulate sum(p) and sum(p*d)
        const int k0 = kt * 128;
#pragma unroll
        for (int mb = 0; mb < 2; mb++) {
            const int r0 = q0 + 32 * mg + 16 * mb + tg;
#pragma unroll
            for (int nb = 0; nb < 8; nb++) {
                float* a = acc[mb][nb];
                int d0 = k0 + 64 * ng + 8 * nb + 2 * tm - r0;
                float fd = (float)d0;
                float s0 = a[0] * __ldg(pt + d0);
                float s1 = a[1] * __ldg(pt + d0 + 1);
                float s2 = a[2] * __ldg(pt + d0 - 8);
                float s3 = a[3] * __ldg(pt + d0 - 7);
                float p0 = __expf(s0), p1 = __expf(s1);
                float p2 = __expf(s2), p3 = __expf(s3);
                suml[2 * mb]     += p0 + p1;
                sumd[2 * mb]     += fmaf(p1, fd + 1.f, p0 * fd);
                suml[2 * mb + 1] += p2 + p3;
                sumd[2 * mb + 1] += fmaf(p3, fd - 7.f, p2 * (fd - 8.f));
            }
        }

        if (kt < 15) cpa_wait0();
        __syncthreads();
    }

    // reduce across the 4 lanes of each group (width-4 shuffles)
#pragma unroll
    for (int s = 0; s < 4; s++) {
        suml[s] += __shfl_xor_sync(0xffffffffu, suml[s], 1, 4);
        suml[s] += __shfl_xor_sync(0xffffffffu, suml[s], 2, 4);
        sumd[s] += __shfl_xor_sync(0xffffffffu, sumd[s], 1, 4);
        sumd[s] += __shfl_xor_sync(0xffffffffu, sumd[s], 2, 4);
    }

    // merge the two n-groups via smem
    if (ng == 0 && tm == 0) {
#pragma unroll
        for (int s = 0; s < 4; s++) {
            int rl = 32 * mg + 16 * (s >> 1) + 8 * (s & 1) + tg;
            merge[rl] = suml[s];
            merge[128 + rl] = sumd[s];
        }
    }
    __syncthreads();
    if (ng == 1 && tm == 0) {
#pragma unroll
        for (int s = 0; s < 4; s++) {
            int rl = 32 * mg + 16 * (s >> 1) + 8 * (s & 1) + tg;
            float Lm = merge[rl] + suml[s];
            float Dm = merge[128 + rl] + sumd[s];
            out[((size_t)(hb & 3) * 2048 + q0 + rl) * 8 + h] = Dm * INV_ML / Lm;
        }
    }
}

// ============================================================
extern "C" void kernel_launch(void* const* d_in, const int* in_sizes, int n_in,
                              void* d_out, int out_size)
{
    const float* x  = (const float*)d_in[0];
    const float* Wq = (const float*)d_in[1];
    const float* bq = (const float*)d_in[2];
    const float* Wk = (const float*)d_in[3];
    const float* bk = (const float*)d_in[4];
    const float* pm = (const float*)d_in[5];
    const float* ls = (const float*)d_in[6];
    float* out = (float*)d_out;

    cudaFuncSetAttribute(proj_kernel,
                         cudaFuncAttributeMaxDynamicSharedMemorySize, PJ_SMEM);
    cudaFuncSetAttribute(flash_kernel,
                         cudaFuncAttributeMaxDynamicSharedMemorySize, FL_SMEM);

    ptab_kernel<<<8, 512>>>(pm, ls);
    conv_x_kernel<<<2048, 256>>>(x);
    conv_w_kernel<<<dim3(16, 8, 2), dim3(32, 8)>>>(Wq, Wk);
    proj_kernel<<<dim3(64, 8), 256, PJ_SMEM>>>(bq, bk);
    flash_kernel<<<dim3(16, 32), 256, FL_SMEM>>>(out);
}